// round 10
// baseline (speedup 1.0000x reference)
#include <cuda_runtime.h>
#include <math.h>

#define BB 256
#define TT 512
#define KK 256

typedef unsigned long long ull;

// scratch for xU [B*T, K] = 134MB (static device global: no runtime alloc)
__device__ float g_xu[(size_t)BB * TT * KK];

#define FMA2(d, a, b) \
    asm("fma.rn.f32x2 %0, %1, %2, %0;" : "+l"(d) : "l"(a), "l"(b))
#define ADD2(d, s) \
    asm("add.rn.f32x2 %0, %0, %1;" : "+l"(d) : "l"(s))
#define UNPK(x, y, v) \
    asm("mov.b64 {%0, %1}, %2;" : "=f"(x), "=f"(y) : "l"(v))

__device__ __forceinline__ ull splat(float x) {
    ull r;
    asm("mov.b64 %0, {%1, %1};" : "=l"(r) : "f"(x));
    return r;
}

// ---------------------------------------------------------------------------
// Phase 1: C[m][n] = sum_d A[m][d] * U[d][n],  M=131072, N=K=256
// CTA tile 128x128, 256 threads, 8x8 microtile via packed f32x2.
// A tile duplicated in smem ({a,a} splats load as 64-bit words).
// DOUBLE-BUFFERED: next tile prefetched into registers during the FMA phase,
// stored to the alternate smem buffer, ONE barrier per kc-iteration.
// ---------------------------------------------------------------------------
__global__ __launch_bounds__(256) void xu_gemm(const float* __restrict__ A,
                                               const float* __restrict__ U) {
    __shared__ float Asd[2][16][256];  // [buf][k][2r],[2r+1] duplicated A
    __shared__ float Bs[2][16][128];   // [buf][k][n]

    const int tid = threadIdx.x;
    const int m0 = (blockIdx.x >> 1) * 128;
    const int n0 = (blockIdx.x & 1) * 128;
    const int tx = tid & 15;   // cols tx*4..+3 and 64+tx*4..+3
    const int ty = tid >> 4;   // rows ty*8 .. +7

    // per-thread load coordinates (2 chunks each for A and B)
    const int ar0 = (tid * 2) >> 2;            // A row 0..127 (chunk 0)
    const int ak0 = ((tid * 2) & 3) * 4;       // A k-offset
    const int ar1 = (tid * 2 + 1) >> 2;
    const int ak1 = ((tid * 2 + 1) & 3) * 4;
    const int br0 = (tid * 2) >> 5;            // B row 0..15
    const int bc0 = ((tid * 2) & 31) * 4;
    const int br1 = (tid * 2 + 1) >> 5;
    const int bc1 = ((tid * 2 + 1) & 31) * 4;

    ull acc[8][4];
#pragma unroll
    for (int i = 0; i < 8; i++)
#pragma unroll
        for (int j = 0; j < 4; j++) acc[i][j] = 0ull;

    // initial load of tile kc=0 into buffer 0
    {
        float4 fa0 = *reinterpret_cast<const float4*>(&A[(size_t)(m0 + ar0) * 256 + ak0]);
        float4 fa1 = *reinterpret_cast<const float4*>(&A[(size_t)(m0 + ar1) * 256 + ak1]);
        float4 fb0 = *reinterpret_cast<const float4*>(&U[(size_t)br0 * 256 + n0 + bc0]);
        float4 fb1 = *reinterpret_cast<const float4*>(&U[(size_t)br1 * 256 + n0 + bc1]);
        *reinterpret_cast<float2*>(&Asd[0][ak0 + 0][2 * ar0]) = make_float2(fa0.x, fa0.x);
        *reinterpret_cast<float2*>(&Asd[0][ak0 + 1][2 * ar0]) = make_float2(fa0.y, fa0.y);
        *reinterpret_cast<float2*>(&Asd[0][ak0 + 2][2 * ar0]) = make_float2(fa0.z, fa0.z);
        *reinterpret_cast<float2*>(&Asd[0][ak0 + 3][2 * ar0]) = make_float2(fa0.w, fa0.w);
        *reinterpret_cast<float2*>(&Asd[0][ak1 + 0][2 * ar1]) = make_float2(fa1.x, fa1.x);
        *reinterpret_cast<float2*>(&Asd[0][ak1 + 1][2 * ar1]) = make_float2(fa1.y, fa1.y);
        *reinterpret_cast<float2*>(&Asd[0][ak1 + 2][2 * ar1]) = make_float2(fa1.z, fa1.z);
        *reinterpret_cast<float2*>(&Asd[0][ak1 + 3][2 * ar1]) = make_float2(fa1.w, fa1.w);
        *reinterpret_cast<float4*>(&Bs[0][br0][bc0]) = fb0;
        *reinterpret_cast<float4*>(&Bs[0][br1][bc1]) = fb1;
    }
    __syncthreads();

    int buf = 0;
    for (int kc = 0; kc < 256; kc += 16) {
        // prefetch next tile into registers (wraps harmlessly on last iter)
        const int kcn = (kc + 16) & 255;
        float4 fa0 = *reinterpret_cast<const float4*>(&A[(size_t)(m0 + ar0) * 256 + kcn + ak0]);
        float4 fa1 = *reinterpret_cast<const float4*>(&A[(size_t)(m0 + ar1) * 256 + kcn + ak1]);
        float4 fb0 = *reinterpret_cast<const float4*>(&U[(size_t)(kcn + br0) * 256 + n0 + bc0]);
        float4 fb1 = *reinterpret_cast<const float4*>(&U[(size_t)(kcn + br1) * 256 + n0 + bc1]);

        // FMA phase over current buffer
#pragma unroll
        for (int k = 0; k < 16; k++) {
            ulonglong2 A01 = *reinterpret_cast<ulonglong2*>(&Asd[buf][k][ty * 16 + 0]);
            ulonglong2 A23 = *reinterpret_cast<ulonglong2*>(&Asd[buf][k][ty * 16 + 4]);
            ulonglong2 A45 = *reinterpret_cast<ulonglong2*>(&Asd[buf][k][ty * 16 + 8]);
            ulonglong2 A67 = *reinterpret_cast<ulonglong2*>(&Asd[buf][k][ty * 16 + 12]);
            ulonglong2 B01 = *reinterpret_cast<ulonglong2*>(&Bs[buf][k][tx * 4]);
            ulonglong2 B23 = *reinterpret_cast<ulonglong2*>(&Bs[buf][k][64 + tx * 4]);
            ull ad[8] = {A01.x, A01.y, A23.x, A23.y, A45.x, A45.y, A67.x, A67.y};
            ull bp[4] = {B01.x, B01.y, B23.x, B23.y};
#pragma unroll
            for (int i = 0; i < 8; i++)
#pragma unroll
                for (int j = 0; j < 4; j++) FMA2(acc[i][j], ad[i], bp[j]);
        }

        // store prefetched tile into the other buffer (no race: different buf)
        const int nb = buf ^ 1;
        *reinterpret_cast<float2*>(&Asd[nb][ak0 + 0][2 * ar0]) = make_float2(fa0.x, fa0.x);
        *reinterpret_cast<float2*>(&Asd[nb][ak0 + 1][2 * ar0]) = make_float2(fa0.y, fa0.y);
        *reinterpret_cast<float2*>(&Asd[nb][ak0 + 2][2 * ar0]) = make_float2(fa0.z, fa0.z);
        *reinterpret_cast<float2*>(&Asd[nb][ak0 + 3][2 * ar0]) = make_float2(fa0.w, fa0.w);
        *reinterpret_cast<float2*>(&Asd[nb][ak1 + 0][2 * ar1]) = make_float2(fa1.x, fa1.x);
        *reinterpret_cast<float2*>(&Asd[nb][ak1 + 1][2 * ar1]) = make_float2(fa1.y, fa1.y);
        *reinterpret_cast<float2*>(&Asd[nb][ak1 + 2][2 * ar1]) = make_float2(fa1.z, fa1.z);
        *reinterpret_cast<float2*>(&Asd[nb][ak1 + 3][2 * ar1]) = make_float2(fa1.w, fa1.w);
        *reinterpret_cast<float4*>(&Bs[nb][br0][bc0]) = fb0;
        *reinterpret_cast<float4*>(&Bs[nb][br1][bc1]) = fb1;
        __syncthreads();
        buf = nb;
    }

#pragma unroll
    for (int i = 0; i < 8; i++) {
        float* Crow = &g_xu[(size_t)(m0 + ty * 8 + i) * 256 + n0];
        float v0, v1, v2, v3, v4, v5, v6, v7;
        UNPK(v0, v1, acc[i][0]);
        UNPK(v2, v3, acc[i][1]);
        UNPK(v4, v5, acc[i][2]);
        UNPK(v6, v7, acc[i][3]);
        *reinterpret_cast<float4*>(Crow + tx * 4)      = make_float4(v0, v1, v2, v3);
        *reinterpret_cast<float4*>(Crow + 64 + tx * 4) = make_float4(v4, v5, v6, v7);
    }
}

// ---------------------------------------------------------------------------
// Phase 2: persistent batch-parallel recurrence. 128 CTAs x 2 batch rows,
// 512 threads. (UNCHANGED from the 622us-passing version.)
// Mainloop (c = tid&127, q = tid>>7): cols {2c,2c+1}, k in [64q, 64q+64).
//   k-pairs [0,14): smem W in PAIRED float4 layout (one LDS.128 = 2 k-steps).
//   k rows [64q+28,64q+64): wt[36] registers.
// 4 accumulator chains merged with add.rn.f32x2.
// Epilogue (col = tid&255, row = tid>>8): one output element per thread.
// ---------------------------------------------------------------------------
__global__ __launch_bounds__(512, 1) void rnn_scan(const float* __restrict__ Wg,
                                                   const float* __restrict__ bg,
                                                   float* __restrict__ out) {
    extern __shared__ float smem[];
    float4*     Wp   = reinterpret_cast<float4*>(smem);               // 112KB
    float2*     hb2  = reinterpret_cast<float2*>(smem + 28672);       // 4KB
    ulonglong2* redu = reinterpret_cast<ulonglong2*>(smem + 28672 + 1024); // 8KB

    const int tid = threadIdx.x;
    const int c   = tid & 127;
    const int cc  = 2 * c;
    const int q   = tid >> 7;        // K-quarter 0..3
    const int col = tid & 255;       // epilogue column
    const int row = tid >> 8;        // epilogue batch row (0/1)
    const int b0  = blockIdx.x * 2;

    // Build paired-k W smem: p = ((qq*14 + j2)*128 + c2)
    for (int p = tid; p < 4 * 14 * 128; p += 512) {
        int qq  = p / (14 * 128);
        int rem = p - qq * 14 * 128;
        int j2  = rem >> 7;
        int c2  = rem & 127;
        int k   = 64 * qq + 2 * j2;
        float2 w0 = *reinterpret_cast<const float2*>(&Wg[(size_t)k * 256 + 2 * c2]);
        float2 w1 = *reinterpret_cast<const float2*>(&Wg[(size_t)(k + 1) * 256 + 2 * c2]);
        Wp[p] = make_float4(w0.x, w0.y, w1.x, w1.y);
    }
    // register-resident W: k in [64q+28, 64q+64), cols {cc, cc+1}
    ull wt[36];
    {
        const int kb = 64 * q + 28;
#pragma unroll
        for (int j = 0; j < 36; j++)
            wt[j] = *reinterpret_cast<const ull*>(&Wg[(size_t)(kb + j) * 256 + cc]);
    }
    // zero both h buffers (512 float2, one per thread)
    hb2[tid] = make_float2(0.f, 0.f);

    const float  bcol = bg[col];
    const float* xp   = &g_xu[((size_t)(b0 + row) * TT) * 256 + col];
    float cur  = xp[0];
    float last = 0.f;
    __syncthreads();

    int rb = 0;
    const ulonglong2* wq =
        reinterpret_cast<const ulonglong2*>(Wp) + ((size_t)q * 14 * 128 + c);
    for (int t = 0; t < TT; t++) {
        // prefetch next step's xu element (hidden under the FMA chain)
        float nxt = cur;
        if (t + 1 < TT) nxt = xp[(size_t)(t + 1) * 256];

        const float4* hq4 =
            reinterpret_cast<const float4*>(hb2 + rb * 256 + q * 64);
        ull a0 = 0ull, a1 = 0ull, e0 = 0ull, e1 = 0ull;
#pragma unroll
        for (int j2 = 0; j2 < 14; j2++) {   // k = 64q+2j2, +1   (smem W, paired)
            float4     hv = hq4[j2];        // {h0[k],h1[k],h0[k+1],h1[k+1]}
            ulonglong2 wv = wq[(size_t)j2 * 128];  // {W[k][cc..], W[k+1][cc..]}
            FMA2(a0, splat(hv.x), wv.x);
            FMA2(a1, splat(hv.y), wv.x);
            FMA2(e0, splat(hv.z), wv.y);
            FMA2(e1, splat(hv.w), wv.y);
        }
#pragma unroll
        for (int j2 = 14; j2 < 32; j2++) {  // k = 64q+2j2, +1   (register W)
            float4 hv = hq4[j2];
            ull w0 = wt[2 * j2 - 28];
            ull w1 = wt[2 * j2 - 27];
            FMA2(a0, splat(hv.x), w0);
            FMA2(a1, splat(hv.y), w0);
            FMA2(e0, splat(hv.z), w1);
            FMA2(e1, splat(hv.w), w1);
        }
        ADD2(a0, e0);
        ADD2(a1, e1);
        // partials: floats [r0:cc, r0:cc+1, r1:cc, r1:cc+1]
        redu[q * 128 + c] = make_ulonglong2(a0, a1);
        __syncthreads();

        // epilogue: one output element per thread
        {
            const float* rf = reinterpret_cast<const float*>(redu);
            const int    fo = ((col >> 1) << 2) + row * 2 + (col & 1);
            float s = cur + bcol;
#pragma unroll
            for (int qq = 0; qq < 4; qq++) s += rf[qq * 512 + fo];
            last = tanhf(s);
            float* hw = reinterpret_cast<float*>(&hb2[(1 - rb) * 256 + col]);
            hw[row] = last;
        }
        __syncthreads();
        cur = nxt;
        rb ^= 1;
    }

    out[(size_t)(b0 + row) * 256 + col] = last;
}

extern "C" void kernel_launch(void* const* d_in, const int* in_sizes, int n_in,
                              void* d_out, int out_size) {
    const float* inputs = (const float*)d_in[0];  // [B,T,D]
    const float* U      = (const float*)d_in[1];  // [D,K]
    const float* W      = (const float*)d_in[2];  // [K,K]
    const float* b      = (const float*)d_in[3];  // [K]
    float* out          = (float*)d_out;          // [B,1,K]

    xu_gemm<<<2048, 256>>>(inputs, U);

    const int smem_bytes = 114688 + 4096 + 8192;  // paired W + h bufs + partials
    cudaFuncSetAttribute(rnn_scan, cudaFuncAttributeMaxDynamicSharedMemorySize,
                         smem_bytes);
    rnn_scan<<<128, 512, smem_bytes>>>(W, b, out);
}